// round 13
// baseline (speedup 1.0000x reference)
#include <cuda_runtime.h>
#include <cuda_bf16.h>
#include <cstdint>

#define BATCH  512
#define N_NODE 200
#define C_IN   200
#define HIDDEN 128

typedef unsigned long long ull;

// ===================== PTX helpers =====================
__device__ __forceinline__ uint32_t smem_u32(const void* p) {
    uint32_t a;
    asm("{ .reg .u64 t; cvta.to.shared.u64 t, %1; cvt.u32.u64 %0, t; }"
        : "=r"(a) : "l"(p));
    return a;
}

#define LDSM_X4(r0, r1, r2, r3, addr) \
    asm volatile("ldmatrix.sync.aligned.m8n8.x4.shared.b16 {%0,%1,%2,%3}, [%4];" \
        : "=r"(r0), "=r"(r1), "=r"(r2), "=r"(r3) : "r"(addr))

#define LDSM_X4T(r0, r1, r2, r3, addr) \
    asm volatile("ldmatrix.sync.aligned.m8n8.x4.trans.shared.b16 {%0,%1,%2,%3}, [%4];" \
        : "=r"(r0), "=r"(r1), "=r"(r2), "=r"(r3) : "r"(addr))

#define MMA16816(c, a0, a1, a2, a3, b0, b1) \
    asm volatile("mma.sync.aligned.m16n8k16.row.col.f32.bf16.bf16.f32 " \
        "{%0,%1,%2,%3}, {%4,%5,%6,%7}, {%8,%9}, {%0,%1,%2,%3};" \
        : "+f"((c)[0]), "+f"((c)[1]), "+f"((c)[2]), "+f"((c)[3]) \
        : "r"(a0), "r"(a1), "r"(a2), "r"(a3), "r"(b0), "r"(b1))

#define CP_ASYNC16(dst, src) \
    asm volatile("cp.async.cg.shared.global [%0], [%1], 16;" \
        :: "r"(dst), "l"(src) : "memory")
#define CP_ASYNC_WAIT_ALL() \
    asm volatile("cp.async.commit_group;\n\tcp.async.wait_group 0;" ::: "memory")

__device__ __forceinline__ void split2(float a, float b, uint32_t& hp, uint32_t& lp) {
    __nv_bfloat16 h0 = __float2bfloat16(a);
    __nv_bfloat16 h1 = __float2bfloat16(b);
    __nv_bfloat16 l0 = __float2bfloat16(a - __bfloat162float(h0));
    __nv_bfloat16 l1 = __float2bfloat16(b - __bfloat162float(h1));
    hp = (uint32_t)__bfloat16_as_ushort(h0) | ((uint32_t)__bfloat16_as_ushort(h1) << 16);
    lp = (uint32_t)__bfloat16_as_ushort(l0) | ((uint32_t)__bfloat16_as_ushort(l1) << 16);
}

// scratch: xw = x @ W1 as bf16 hi/lo, [BATCH, N_NODE, 128] each
__device__ __nv_bfloat16 g_xwhi[(size_t)BATCH * N_NODE * HIDDEN];
__device__ __nv_bfloat16 g_xwlo[(size_t)BATCH * N_NODE * HIDDEN];
// W1 pre-split into bf16 hi/lo, zero-padded to K=208 rows: [208][128]
__device__ __nv_bfloat16 g_w1hi[208 * HIDDEN];
__device__ __nv_bfloat16 g_w1lo[208 * HIDDEN];
// per-quad partial graph sums: [BATCH*4][2]
__device__ float g_part[BATCH * 4 * 2];

// ---------------------------------------------------------------------------
// K0: split W1 fp32 -> bf16 hi/lo with zero k-padding (runs once, tiny)
// ---------------------------------------------------------------------------
__global__ void split_w1_kernel(const float* __restrict__ W1)
{
    int idx = blockIdx.x * 256 + threadIdx.x;
    if (idx >= 208 * HIDDEN) return;
    int k = idx / HIDDEN;
    float v = (k < C_IN) ? W1[idx] : 0.f;
    __nv_bfloat16 h = __float2bfloat16(v);
    __nv_bfloat16 l = __float2bfloat16(v - __bfloat162float(h));
    g_w1hi[idx] = h;
    g_w1lo[idx] = l;
}

// ---------------------------------------------------------------------------
// K1: xw = x @ W1 via mma.sync split-bf16 (unchanged from round 12)
// ---------------------------------------------------------------------------
#define K1_PA     432
#define K1_PB     272
#define K1_AHI    0
#define K1_ALO    55296
#define K1_BHI    110592
#define K1_BLO    167168
#define K1_SMEM   223744

__global__ __launch_bounds__(512, 1) void gemm_xw_mma_kernel(
    const float* __restrict__ x)
{
    extern __shared__ char smem[];
    const uint32_t sbase = smem_u32(smem);

    const int m0   = blockIdx.x * 128;
    const int t    = threadIdx.x;
    const int w    = t >> 5;
    const int lane = t & 31;

    for (int idx = t; idx < 208 * 16; idx += 512) {
        const int r = idx >> 4;
        const int c = idx & 15;
        CP_ASYNC16(sbase + K1_BHI + r * K1_PB + c * 16,
                   (const char*)g_w1hi + r * 256 + c * 16);
        CP_ASYNC16(sbase + K1_BLO + r * K1_PB + c * 16,
                   (const char*)g_w1lo + r * 256 + c * 16);
    }

    for (int idx = t; idx < 128 * 50; idx += 512) {
        const int m = idx / 50;
        const int q = idx % 50;
        float4 v = *(const float4*)&x[(size_t)(m0 + m) * C_IN + q * 4];
        uint2 hp, lp;
        split2(v.x, v.y, hp.x, lp.x);
        split2(v.z, v.w, hp.y, lp.y);
        *(uint2*)(smem + K1_AHI + m * K1_PA + q * 8) = hp;
        *(uint2*)(smem + K1_ALO + m * K1_PA + q * 8) = lp;
    }
    if (t < 128) {
        *(uint4*)(smem + K1_AHI + t * K1_PA + 400) = make_uint4(0u, 0u, 0u, 0u);
        *(uint4*)(smem + K1_ALO + t * K1_PA + 400) = make_uint4(0u, 0u, 0u, 0u);
    }
    CP_ASYNC_WAIT_ALL();
    __syncthreads();

    const int mt = w & 7;
    const int nh = w >> 3;

    float acc[8][4];
#pragma unroll
    for (int n = 0; n < 8; n++) {
        acc[n][0] = 0.f; acc[n][1] = 0.f; acc[n][2] = 0.f; acc[n][3] = 0.f;
    }

    const uint32_t ah_base = sbase + K1_AHI
        + (uint32_t)(16 * mt + (lane & 15)) * K1_PA + (uint32_t)(lane >> 4) * 16;
    const uint32_t al_base = ah_base + (K1_ALO - K1_AHI);
    const uint32_t b_off   = (uint32_t)(lane & 15) * K1_PB + (uint32_t)(lane >> 4) * 16
                           + (uint32_t)nh * 128;
    const uint32_t bhi_base = sbase + K1_BHI + b_off;
    const uint32_t blo_base = sbase + K1_BLO + b_off;

#pragma unroll 1
    for (int ks = 0; ks < 13; ks++) {
        uint32_t ah0, ah1, ah2, ah3, al0, al1, al2, al3;
        LDSM_X4(ah0, ah1, ah2, ah3, ah_base + (uint32_t)ks * 32);
        LDSM_X4(al0, al1, al2, al3, al_base + (uint32_t)ks * 32);
        const uint32_t brow = (uint32_t)ks * 16 * K1_PB;
#pragma unroll
        for (int nb = 0; nb < 4; nb++) {
            uint32_t h0, h1, h2, h3, l0, l1, l2, l3;
            LDSM_X4T(h0, h1, h2, h3, bhi_base + brow + (uint32_t)nb * 32);
            MMA16816(acc[2 * nb],     ah0, ah1, ah2, ah3, h0, h1);
            MMA16816(acc[2 * nb + 1], ah0, ah1, ah2, ah3, h2, h3);
            MMA16816(acc[2 * nb],     al0, al1, al2, al3, h0, h1);
            MMA16816(acc[2 * nb + 1], al0, al1, al2, al3, h2, h3);
            LDSM_X4T(l0, l1, l2, l3, blo_base + brow + (uint32_t)nb * 32);
            MMA16816(acc[2 * nb],     ah0, ah1, ah2, ah3, l0, l1);
            MMA16816(acc[2 * nb + 1], ah0, ah1, ah2, ah3, l2, l3);
        }
    }

    const int g  = lane >> 2;
    const int tg = lane & 3;
    const size_t ra = (size_t)(m0 + 16 * mt + g) * HIDDEN;
    const size_t rb = ra + 8 * HIDDEN;
    uint32_t* xh = (uint32_t*)g_xwhi;
    uint32_t* xl = (uint32_t*)g_xwlo;
#pragma unroll
    for (int nt = 0; nt < 8; nt++) {
        const int f = nh * 64 + nt * 8 + tg * 2;
        uint32_t hp, lp;
        split2(acc[nt][0], acc[nt][1], hp, lp);
        xh[(ra + f) >> 1] = hp;
        xl[(ra + f) >> 1] = lp;
        split2(acc[nt][2], acc[nt][3], hp, lp);
        xh[(rb + f) >> 1] = hp;
        xl[(rb + f) >> 1] = lp;
    }
}

// ---------------------------------------------------------------------------
// K2: quad-split GIN aggregation. grid = BATCH*4; CTA = (batch, j-half, f-half).
//   M = 100 (pad 112), N = 64, K = 208. 256 threads, 2 CTAs/SM (~111KB smem).
//   Emits partial graph sums to g_part; K3 combines.
// ---------------------------------------------------------------------------
#define Q_PA      240                 // A row pitch bytes (112 cols bf16 + pad)
#define Q_PB      144                 // B row pitch bytes (64 cols bf16 + pad)
#define Q_A       0                   // 208*240 = 49920
#define Q_BHI     49920               // 208*144 = 29952
#define Q_BLO     79872
#define Q_DEG     109824              // 100 floats
#define Q_WS      110224              // 8*2 floats
#define Q_B1S     110288              // 64 floats
#define Q_W2S     110544              // 128 floats
#define Q_SMEM    111104

__global__ __launch_bounds__(256, 2) void gin_quad_kernel(
    const int*   __restrict__ adj,
    const float* __restrict__ b1,
    const float* __restrict__ W2,
    const float* __restrict__ eps1p,
    const float* __restrict__ eps2p)
{
    extern __shared__ char smem[];
    const uint32_t sbase = smem_u32(smem);
    float* degs = (float*)(smem + Q_DEG);
    float* wsum = (float*)(smem + Q_WS);
    float* b1s  = (float*)(smem + Q_B1S);
    float* w2s  = (float*)(smem + Q_W2S);

    const int b    = blockIdx.x >> 2;
    const int jh   = (blockIdx.x >> 1) & 1;
    const int fh   = blockIdx.x & 1;
    const int j0   = jh * 100;
    const int f0   = fh * 64;
    const int t    = threadIdx.x;
    const int w    = t >> 5;
    const int lane = t & 31;
    const int* adj_b = adj + (size_t)b * N_NODE * N_NODE;

    // ---- cp.async B: xw[b][i][f0..f0+63] hi/lo, 200 rows x 8 x 16B ----
    {
        const char* srch = (const char*)g_xwhi + (size_t)b * N_NODE * 256 + f0 * 2;
        const char* srcl = (const char*)g_xwlo + (size_t)b * N_NODE * 256 + f0 * 2;
        for (int idx = t; idx < 200 * 8; idx += 256) {
            const int r = idx >> 3;
            const int c = idx & 7;
            CP_ASYNC16(sbase + Q_BHI + r * Q_PB + c * 16, srch + r * 256 + c * 16);
            CP_ASYNC16(sbase + Q_BLO + r * Q_PB + c * 16, srcl + r * 256 + c * 16);
        }
    }

    // ---- pad zeroing ----
    {
        const uint4 z16 = make_uint4(0u, 0u, 0u, 0u);
        // A col pad bytes [200,240) rows 0..199
        for (int r = t; r < 200; r += 256) {
            char* p = smem + Q_A + r * Q_PA;
            *(ull*)(p + 200) = 0ull;
            *(uint4*)(p + 208) = z16;
            *(uint4*)(p + 224) = z16;
        }
        // A rows 200..207 full (15 x 16B)
        for (int idx = t; idx < 8 * 15; idx += 256) {
            const int r = 200 + idx / 15;
            const int c = idx % 15;
            *(uint4*)(smem + Q_A + r * Q_PA + c * 16) = z16;
        }
        // B rows 200..207 (hi/lo), 9 x 16B each
        for (int idx = t; idx < 2 * 8 * 9; idx += 256) {
            const int buf = idx >= 72;
            const int k = idx - buf * 72;
            const int r = 200 + k / 9;
            const int c = k % 9;
            *(uint4*)(smem + (buf ? Q_BLO : Q_BHI) + r * Q_PB + c * 16) = z16;
        }
        if (t < 64)  b1s[t] = b1[f0 + t];
        if (t < 128) w2s[t] = W2[f0 * 2 + t];
    }

    // ---- stage A: adj[i][j0+jl], jl 0..99 (non-transposed) ----
    for (int i = w; i < N_NODE; i += 8) {
        const int* row = &adj_b[i * N_NODE + j0];
        char* dst = smem + Q_A + i * Q_PA;
#pragma unroll
        for (int c = 0; c < 4; c++) {
            const int jl = lane + 32 * c;
            if (jl < 100)
                *(unsigned short*)(dst + jl * 2) =
                    row[jl] ? (unsigned short)0x3F80u : (unsigned short)0u;
        }
    }
    // ---- degrees for OUR output nodes: degs[r] = row-sum of adj row (j0+r) ----
    for (int r = w; r < 100; r += 8) {
        const int* row = &adj_b[(j0 + r) * N_NODE];
        int rsum = 0;
#pragma unroll
        for (int c = 0; c < 7; c++) {
            const int k = lane + 32 * c;
            if (k < N_NODE) rsum += row[k];
        }
#pragma unroll
        for (int off = 16; off; off >>= 1)
            rsum += __shfl_xor_sync(0xffffffffu, rsum, off);
        if (lane == 0) degs[r] = (float)rsum;
    }
    CP_ASYNC_WAIT_ALL();
    __syncthreads();

    // ---- MMA + epilogue (warps 0..6; warp w owns jl = 16w..16w+15) ----
    if (w < 7) {
        float acc[8][4];
#pragma unroll
        for (int n = 0; n < 8; n++) {
            acc[n][0] = 0.f; acc[n][1] = 0.f; acc[n][2] = 0.f; acc[n][3] = 0.f;
        }

        const uint32_t a_base = sbase + Q_A
            + (uint32_t)((lane & 7) + ((lane >> 4) << 3)) * Q_PA
            + (uint32_t)(16 * w + ((lane >> 3) & 1) * 8) * 2;
        const uint32_t b_off = (uint32_t)(lane & 15) * Q_PB + (uint32_t)(lane >> 4) * 16;
        const uint32_t bhi_base = sbase + Q_BHI + b_off;
        const uint32_t blo_base = sbase + Q_BLO + b_off;

#pragma unroll 1
        for (int ks = 0; ks < 13; ks++) {
            uint32_t a0, a1, a2, a3;
            LDSM_X4T(a0, a1, a2, a3, a_base + (uint32_t)ks * 16 * Q_PA);
            const uint32_t brow = (uint32_t)ks * 16 * Q_PB;
#pragma unroll
            for (int nb = 0; nb < 4; nb++) {
                uint32_t h0, h1, h2, h3, l0, l1, l2, l3;
                LDSM_X4T(h0, h1, h2, h3, bhi_base + brow + (uint32_t)nb * 32);
                MMA16816(acc[2 * nb],     a0, a1, a2, a3, h0, h1);
                MMA16816(acc[2 * nb + 1], a0, a1, a2, a3, h2, h3);
                LDSM_X4T(l0, l1, l2, l3, blo_base + brow + (uint32_t)nb * 32);
                MMA16816(acc[2 * nb],     a0, a1, a2, a3, l0, l1);
                MMA16816(acc[2 * nb + 1], a0, a1, a2, a3, l2, l3);
            }
        }

        const float c1x = 1.f + *eps1p;
        const float c2x = 1.f + *eps2p;
        const int g  = lane >> 2;
        const int tg = lane & 3;
        const int jla = 16 * w + g;          // local output node (valid if <100)
        const int jlb = jla + 8;
        const int rowa = j0 + min(jla, 99);  // clamped smem B row (finite data)
        const int rowb = j0 + min(jlb, 99);

        float pa0 = 0.f, pa1 = 0.f, pb0 = 0.f, pb1 = 0.f;
#pragma unroll
        for (int nt = 0; nt < 8; nt++) {
            const int fl = nt * 8 + tg * 2;
            uint32_t ha = *(uint32_t*)(smem + Q_BHI + rowa * Q_PB + fl * 2);
            uint32_t la = *(uint32_t*)(smem + Q_BLO + rowa * Q_PB + fl * 2);
            uint32_t hb = *(uint32_t*)(smem + Q_BHI + rowb * Q_PB + fl * 2);
            uint32_t lb = *(uint32_t*)(smem + Q_BLO + rowb * Q_PB + fl * 2);
            float xa0 = __uint_as_float(ha << 16) + __uint_as_float(la << 16);
            float xa1 = __uint_as_float(ha & 0xFFFF0000u) + __uint_as_float(la & 0xFFFF0000u);
            float xb0 = __uint_as_float(hb << 16) + __uint_as_float(lb << 16);
            float xb1 = __uint_as_float(hb & 0xFFFF0000u) + __uint_as_float(lb & 0xFFFF0000u);
            float bv0 = b1s[fl], bv1 = b1s[fl + 1];
            float w00 = w2s[fl * 2],       w01 = w2s[fl * 2 + 1];
            float w10 = w2s[(fl + 1) * 2], w11 = w2s[(fl + 1) * 2 + 1];

            float ha0 = fmaxf(fmaf(c1x, xa0, acc[nt][0]) + bv0, 0.f);
            float ha1 = fmaxf(fmaf(c1x, xa1, acc[nt][1]) + bv1, 0.f);
            float hb0 = fmaxf(fmaf(c1x, xb0, acc[nt][2]) + bv0, 0.f);
            float hb1 = fmaxf(fmaf(c1x, xb1, acc[nt][3]) + bv1, 0.f);

            pa0 += ha0 * w00 + ha1 * w10;
            pa1 += ha0 * w01 + ha1 * w11;
            pb0 += hb0 * w00 + hb1 * w10;
            pb1 += hb0 * w01 + hb1 * w11;
        }
#pragma unroll
        for (int off = 1; off <= 2; off <<= 1) {
            pa0 += __shfl_xor_sync(0xffffffffu, pa0, off);
            pa1 += __shfl_xor_sync(0xffffffffu, pa1, off);
            pb0 += __shfl_xor_sync(0xffffffffu, pb0, off);
            pb1 += __shfl_xor_sync(0xffffffffu, pb1, off);
        }
        // node weights (0 for out-of-range rows kills clamped garbage)
        float wa = (jla < 100) ? (c2x + degs[min(jla, 99)]) : 0.f;
        float wb = (jlb < 100) ? (c2x + degs[min(jlb, 99)]) : 0.f;
        float s0 = (tg == 0) ? (pa0 * wa + pb0 * wb) : 0.f;
        float s1 = (tg == 0) ? (pa1 * wa + pb1 * wb) : 0.f;
#pragma unroll
        for (int off = 4; off <= 16; off <<= 1) {
            s0 += __shfl_xor_sync(0xffffffffu, s0, off);
            s1 += __shfl_xor_sync(0xffffffffu, s1, off);
        }
        if (lane == 0) { wsum[w * 2 + 0] = s0; wsum[w * 2 + 1] = s1; }
    }
    __syncthreads();

    if (t < 2) {
        float s = 0.f;
#pragma unroll
        for (int q = 0; q < 7; q++) s += wsum[q * 2 + t];
        g_part[blockIdx.x * 2 + t] = s;
    }
}

// ---------------------------------------------------------------------------
// K3: combine quad partials -> out (deterministic fixed-order sum)
// ---------------------------------------------------------------------------
__global__ void combine_kernel(const float* __restrict__ b2,
                               float* __restrict__ out)
{
    int idx = blockIdx.x * 256 + threadIdx.x;
    if (idx >= BATCH * 2) return;
    int b = idx >> 1, c = idx & 1;
    float s = g_part[(b * 4 + 0) * 2 + c] + g_part[(b * 4 + 1) * 2 + c]
            + g_part[(b * 4 + 2) * 2 + c] + g_part[(b * 4 + 3) * 2 + c];
    out[idx] = s * (1.f / N_NODE) + b2[c];
}

// ---------------------------------------------------------------------------
extern "C" void kernel_launch(void* const* d_in, const int* in_sizes, int n_in,
                              void* d_out, int out_size)
{
    const float* x    = (const float*)d_in[0];   // [512,200,200]
    const int*   adj  = (const int*)  d_in[1];   // [512,200,200]
    const float* W1   = (const float*)d_in[2];   // [200,128]
    const float* b1   = (const float*)d_in[3];   // [128]
    const float* W2   = (const float*)d_in[4];   // [128,2]
    const float* b2   = (const float*)d_in[5];   // [2]
    const float* eps1 = (const float*)d_in[6];
    const float* eps2 = (const float*)d_in[7];
    float* out = (float*)d_out;                  // [512,2]

    cudaFuncSetAttribute(gemm_xw_mma_kernel,
                         cudaFuncAttributeMaxDynamicSharedMemorySize, K1_SMEM);
    cudaFuncSetAttribute(gin_quad_kernel,
                         cudaFuncAttributeMaxDynamicSharedMemorySize, Q_SMEM);

    split_w1_kernel<<<(208 * HIDDEN + 255) / 256, 256>>>(W1);
    gemm_xw_mma_kernel<<<BATCH * N_NODE / 128, 512, K1_SMEM>>>(x);
    gin_quad_kernel<<<BATCH * 4, 256, Q_SMEM>>>(adj, b1, W2, eps1, eps2);
    combine_kernel<<<4, 256>>>(b2, out);
}

// round 14
// speedup vs baseline: 1.2654x; 1.2654x over previous
#include <cuda_runtime.h>
#include <cuda_bf16.h>
#include <cstdint>

#define BATCH  512
#define N_NODE 200
#define C_IN   200
#define HIDDEN 128

typedef unsigned long long ull;

// ===================== PTX helpers =====================
__device__ __forceinline__ uint32_t smem_u32(const void* p) {
    uint32_t a;
    asm("{ .reg .u64 t; cvta.to.shared.u64 t, %1; cvt.u32.u64 %0, t; }"
        : "=r"(a) : "l"(p));
    return a;
}

#define LDSM_X4(r0, r1, r2, r3, addr) \
    asm volatile("ldmatrix.sync.aligned.m8n8.x4.shared.b16 {%0,%1,%2,%3}, [%4];" \
        : "=r"(r0), "=r"(r1), "=r"(r2), "=r"(r3) : "r"(addr))

#define LDSM_X4T(r0, r1, r2, r3, addr) \
    asm volatile("ldmatrix.sync.aligned.m8n8.x4.trans.shared.b16 {%0,%1,%2,%3}, [%4];" \
        : "=r"(r0), "=r"(r1), "=r"(r2), "=r"(r3) : "r"(addr))

#define MMA16816(c, a0, a1, a2, a3, b0, b1) \
    asm volatile("mma.sync.aligned.m16n8k16.row.col.f32.bf16.bf16.f32 " \
        "{%0,%1,%2,%3}, {%4,%5,%6,%7}, {%8,%9}, {%0,%1,%2,%3};" \
        : "+f"((c)[0]), "+f"((c)[1]), "+f"((c)[2]), "+f"((c)[3]) \
        : "r"(a0), "r"(a1), "r"(a2), "r"(a3), "r"(b0), "r"(b1))

#define CP_ASYNC16(dst, src) \
    asm volatile("cp.async.cg.shared.global [%0], [%1], 16;" \
        :: "r"(dst), "l"(src) : "memory")
#define CP_ASYNC_WAIT_ALL() \
    asm volatile("cp.async.commit_group;\n\tcp.async.wait_group 0;" ::: "memory")

__device__ __forceinline__ void split2(float a, float b, uint32_t& hp, uint32_t& lp) {
    __nv_bfloat16 h0 = __float2bfloat16(a);
    __nv_bfloat16 h1 = __float2bfloat16(b);
    __nv_bfloat16 l0 = __float2bfloat16(a - __bfloat162float(h0));
    __nv_bfloat16 l1 = __float2bfloat16(b - __bfloat162float(h1));
    hp = (uint32_t)__bfloat16_as_ushort(h0) | ((uint32_t)__bfloat16_as_ushort(h1) << 16);
    lp = (uint32_t)__bfloat16_as_ushort(l0) | ((uint32_t)__bfloat16_as_ushort(l1) << 16);
}

// scratch: xw = x @ W1 as bf16 hi/lo, [BATCH, N_NODE, 128] each
__device__ __nv_bfloat16 g_xwhi[(size_t)BATCH * N_NODE * HIDDEN];
__device__ __nv_bfloat16 g_xwlo[(size_t)BATCH * N_NODE * HIDDEN];
// W1 pre-split into bf16 hi/lo, zero-padded to K=208 rows: [208][128]
__device__ __nv_bfloat16 g_w1hi[208 * HIDDEN];
__device__ __nv_bfloat16 g_w1lo[208 * HIDDEN];

// ---------------------------------------------------------------------------
// K0: split W1 fp32 -> bf16 hi/lo with zero k-padding (runs once, tiny)
// ---------------------------------------------------------------------------
__global__ void split_w1_kernel(const float* __restrict__ W1)
{
    int idx = blockIdx.x * 256 + threadIdx.x;
    if (idx >= 208 * HIDDEN) return;
    int k = idx / HIDDEN;
    float v = (k < C_IN) ? W1[idx] : 0.f;
    __nv_bfloat16 h = __float2bfloat16(v);
    __nv_bfloat16 l = __float2bfloat16(v - __bfloat162float(h));
    g_w1hi[idx] = h;
    g_w1lo[idx] = l;
}

// ---------------------------------------------------------------------------
// K1: xw = x @ W1 via mma.sync split-bf16 (3 products: hh + hl + lh).
//   512 threads / 16 warps: warp = (m-slab mp=w&3: m32) x (n-quarter nq=w>>2: n32)
//   B fragments reused across 2 m-tiles -> half the B ldmatrix traffic.
// ---------------------------------------------------------------------------
#define K1_PA     432
#define K1_PB     272
#define K1_AHI    0
#define K1_ALO    55296
#define K1_BHI    110592
#define K1_BLO    167168
#define K1_SMEM   223744

__global__ __launch_bounds__(512, 1) void gemm_xw_mma_kernel(
    const float* __restrict__ x)
{
    extern __shared__ char smem[];
    const uint32_t sbase = smem_u32(smem);

    const int m0   = blockIdx.x * 128;
    const int t    = threadIdx.x;
    const int w    = t >> 5;
    const int lane = t & 31;

    for (int idx = t; idx < 208 * 16; idx += 512) {
        const int r = idx >> 4;
        const int c = idx & 15;
        CP_ASYNC16(sbase + K1_BHI + r * K1_PB + c * 16,
                   (const char*)g_w1hi + r * 256 + c * 16);
        CP_ASYNC16(sbase + K1_BLO + r * K1_PB + c * 16,
                   (const char*)g_w1lo + r * 256 + c * 16);
    }

    for (int idx = t; idx < 128 * 50; idx += 512) {
        const int m = idx / 50;
        const int q = idx % 50;
        float4 v = *(const float4*)&x[(size_t)(m0 + m) * C_IN + q * 4];
        uint2 hp, lp;
        split2(v.x, v.y, hp.x, lp.x);
        split2(v.z, v.w, hp.y, lp.y);
        *(uint2*)(smem + K1_AHI + m * K1_PA + q * 8) = hp;
        *(uint2*)(smem + K1_ALO + m * K1_PA + q * 8) = lp;
    }
    if (t < 128) {
        *(uint4*)(smem + K1_AHI + t * K1_PA + 400) = make_uint4(0u, 0u, 0u, 0u);
        *(uint4*)(smem + K1_ALO + t * K1_PA + 400) = make_uint4(0u, 0u, 0u, 0u);
    }
    CP_ASYNC_WAIT_ALL();
    __syncthreads();

    const int mp = w & 3;          // m-slab: rows 32mp .. 32mp+31
    const int nq = w >> 2;         // n-quarter: cols 32nq .. 32nq+31

    float acc[2][4][4];            // [m-tile][n8-tile][4]
#pragma unroll
    for (int mt = 0; mt < 2; mt++)
#pragma unroll
        for (int n = 0; n < 4; n++) {
            acc[mt][n][0] = 0.f; acc[mt][n][1] = 0.f;
            acc[mt][n][2] = 0.f; acc[mt][n][3] = 0.f;
        }

    const uint32_t ah0_base = sbase + K1_AHI
        + (uint32_t)(32 * mp + (lane & 15)) * K1_PA + (uint32_t)(lane >> 4) * 16;
    const uint32_t ah1_base = ah0_base + 16 * K1_PA;
    const uint32_t al0_base = ah0_base + (K1_ALO - K1_AHI);
    const uint32_t al1_base = ah1_base + (K1_ALO - K1_AHI);
    const uint32_t b_off = (uint32_t)(lane & 15) * K1_PB + (uint32_t)(lane >> 4) * 16
                         + (uint32_t)nq * 64;
    const uint32_t bhi_base = sbase + K1_BHI + b_off;
    const uint32_t blo_base = sbase + K1_BLO + b_off;

#pragma unroll 1
    for (int ks = 0; ks < 13; ks++) {
        uint32_t ah[2][4], al[2][4];
        LDSM_X4(ah[0][0], ah[0][1], ah[0][2], ah[0][3], ah0_base + (uint32_t)ks * 32);
        LDSM_X4(ah[1][0], ah[1][1], ah[1][2], ah[1][3], ah1_base + (uint32_t)ks * 32);
        LDSM_X4(al[0][0], al[0][1], al[0][2], al[0][3], al0_base + (uint32_t)ks * 32);
        LDSM_X4(al[1][0], al[1][1], al[1][2], al[1][3], al1_base + (uint32_t)ks * 32);
        const uint32_t brow = (uint32_t)ks * 16 * K1_PB;
#pragma unroll
        for (int nbg = 0; nbg < 2; nbg++) {
            uint32_t h0, h1, h2, h3, l0, l1, l2, l3;
            LDSM_X4T(h0, h1, h2, h3, bhi_base + brow + (uint32_t)nbg * 32);
#pragma unroll
            for (int mt = 0; mt < 2; mt++) {
                MMA16816(acc[mt][2 * nbg],     ah[mt][0], ah[mt][1], ah[mt][2], ah[mt][3], h0, h1);
                MMA16816(acc[mt][2 * nbg + 1], ah[mt][0], ah[mt][1], ah[mt][2], ah[mt][3], h2, h3);
                MMA16816(acc[mt][2 * nbg],     al[mt][0], al[mt][1], al[mt][2], al[mt][3], h0, h1);
                MMA16816(acc[mt][2 * nbg + 1], al[mt][0], al[mt][1], al[mt][2], al[mt][3], h2, h3);
            }
            LDSM_X4T(l0, l1, l2, l3, blo_base + brow + (uint32_t)nbg * 32);
#pragma unroll
            for (int mt = 0; mt < 2; mt++) {
                MMA16816(acc[mt][2 * nbg],     ah[mt][0], ah[mt][1], ah[mt][2], ah[mt][3], l0, l1);
                MMA16816(acc[mt][2 * nbg + 1], ah[mt][0], ah[mt][1], ah[mt][2], ah[mt][3], l2, l3);
            }
        }
    }

    // ---- epilogue: split fragments to bf16 hi/lo and store ----
    const int g  = lane >> 2;
    const int tg = lane & 3;
    uint32_t* xh = (uint32_t*)g_xwhi;
    uint32_t* xl = (uint32_t*)g_xwlo;
#pragma unroll
    for (int mt = 0; mt < 2; mt++) {
        const size_t ra = (size_t)(m0 + 32 * mp + 16 * mt + g) * HIDDEN;
        const size_t rb = ra + 8 * HIDDEN;
#pragma unroll
        for (int nt = 0; nt < 4; nt++) {
            const int f = 32 * nq + nt * 8 + tg * 2;
            uint32_t hp, lp;
            split2(acc[mt][nt][0], acc[mt][nt][1], hp, lp);
            xh[(ra + f) >> 1] = hp;
            xl[(ra + f) >> 1] = lp;
            split2(acc[mt][nt][2], acc[mt][nt][3], hp, lp);
            xh[(rb + f) >> 1] = hp;
            xl[(rb + f) >> 1] = lp;
        }
    }
}

// ---------------------------------------------------------------------------
// K2: one CTA per batch, 512 threads. mma.sync m16n8k16 bf16 (split hi/lo B).
//   14 MMA warps: warp = (m-slab mp: m32 of M=224 pad) x (n-half nh: n64).
//   B fragments reused across 2 m-tiles. adj staged non-transposed; A via
//   ldmatrix.trans. Degrees fused into A staging. Per-warp partials, no atomics.
// ---------------------------------------------------------------------------
#define PITCH_A_B   464                 // 232 bf16 cols (M pad 224 + spare)
#define PITCH_B_B   272
#define OFF_A       0                   // 208 * 464 = 96512
#define OFF_BHI     96512               // 208 * 272 = 56576
#define OFF_BLO     153088
#define OFF_DEG     209664              // 200 floats -> 800B
#define OFF_WS      210464              // 14*2 floats -> 112B (pad to 128)
#define OFF_B1S     210592              // 128 floats
#define OFF_W2S     211104              // 256 floats
#define SMEM_TOTAL  212160

__global__ __launch_bounds__(512, 1) void gin_fused_kernel(
    const int*   __restrict__ adj,
    const float* __restrict__ b1,
    const float* __restrict__ W2,
    const float* __restrict__ b2,
    const float* __restrict__ eps1p,
    const float* __restrict__ eps2p,
    float*       __restrict__ out)
{
    extern __shared__ char smem[];
    const uint32_t sbase = smem_u32(smem);
    float* degs = (float*)(smem + OFF_DEG);
    float* wsum = (float*)(smem + OFF_WS);
    float* b1s  = (float*)(smem + OFF_B1S);
    float* w2s  = (float*)(smem + OFF_W2S);

    const int b    = blockIdx.x;
    const int t    = threadIdx.x;
    const int w    = t >> 5;
    const int lane = t & 31;
    const int* adj_b = adj + (size_t)b * N_NODE * N_NODE;

    // ---- issue B copies first (cp.async), rows 0..199 of hi and lo ----
    {
        const char* srch = (const char*)g_xwhi + (size_t)b * N_NODE * 256;
        const char* srcl = (const char*)g_xwlo + (size_t)b * N_NODE * 256;
        for (int idx = t; idx < 200 * 16; idx += 512) {
            const int i = idx >> 4;
            const int c = idx & 15;
            CP_ASYNC16(sbase + OFF_BHI + i * PITCH_B_B + c * 16, srch + i * 256 + c * 16);
            CP_ASYNC16(sbase + OFF_BLO + i * PITCH_B_B + c * 16, srcl + i * 256 + c * 16);
        }
    }

    // ---- targeted pad zeroing ----
    {
        const uint4 z = make_uint4(0u, 0u, 0u, 0u);
        // A col-pad bytes [400,464) rows 0..199 (4 x 16B)
        for (int r = t; r < 200; r += 512) {
            char* p = smem + OFF_A + r * PITCH_A_B;
            *(uint4*)(p + 400) = z;
            *(uint4*)(p + 416) = z;
            *(uint4*)(p + 432) = z;
            *(uint4*)(p + 448) = z;
        }
        // A pad rows 200..207: full 464B each (29 uint4)
        for (int idx = t; idx < 8 * 29; idx += 512) {
            const int r = 200 + idx / 29;
            const int c = idx % 29;
            *(uint4*)(smem + OFF_A + r * PITCH_A_B + c * 16) = z;
        }
        // B pad rows 200..207 (hi and lo), 16 uint4 data + keep within pitch
        for (int idx = t; idx < 2 * 8 * 16; idx += 512) {
            const int buf = idx >> 7;
            const int r = 200 + ((idx >> 4) & 7);
            const int c = idx & 15;
            *(uint4*)(smem + (buf ? OFF_BLO : OFF_BHI) + r * PITCH_B_B + c * 16) = z;
        }
        if (t < 128) b1s[t] = b1[t];
        if (t < 256) w2s[t] = W2[t];
    }

    // ---- stage A: adj[i][j] non-transposed (contiguous stores) + ROW degs ----
    {
        for (int i = w; i < N_NODE; i += 16) {
            const int* row = &adj_b[i * N_NODE];
            char* dst = smem + OFF_A + i * PITCH_A_B;
            int rsum = 0;
#pragma unroll
            for (int c = 0; c < 7; c++) {
                const int j = lane + 32 * c;
                if (j < N_NODE) {
                    int v = row[j];
                    *(unsigned short*)(dst + j * 2) =
                        v ? (unsigned short)0x3F80u : (unsigned short)0u;
                    rsum += v;
                }
            }
#pragma unroll
            for (int off = 16; off; off >>= 1)
                rsum += __shfl_xor_sync(0xffffffffu, rsum, off);
            if (lane == 0) degs[i] = (float)rsum;
        }
    }
    CP_ASYNC_WAIT_ALL();
    __syncthreads();

    // ---- MMA + epilogue: warps 0..13, warp = (mp = w%7: rows 32mp..+31,
    //      nh = w/7: cols 64nh..+63) ----
    if (w < 14) {
        const int mp = w % 7;
        const int nh = w / 7;

        float acc[2][8][4];
#pragma unroll
        for (int mt = 0; mt < 2; mt++)
#pragma unroll
            for (int n = 0; n < 8; n++) {
                acc[mt][n][0] = 0.f; acc[mt][n][1] = 0.f;
                acc[mt][n][2] = 0.f; acc[mt][n][3] = 0.f;
            }

        // A via ldmatrix.trans from S[i][j]: row i0+(l&7)+((l>>4)<<3),
        // col (32mp + 16mt) + ((l>>3)&1)*8
        const uint32_t a_row = (uint32_t)((lane & 7) + ((lane >> 4) << 3)) * PITCH_A_B;
        const uint32_t a0_base = sbase + OFF_A + a_row
            + (uint32_t)(32 * mp + ((lane >> 3) & 1) * 8) * 2;
        const uint32_t a1_base = a0_base + 32;          // +16 cols
        const uint32_t b_off = (uint32_t)(lane & 15) * PITCH_B_B
            + (uint32_t)(lane >> 4) * 16 + (uint32_t)nh * 128;
        const uint32_t bhi_base = sbase + OFF_BHI + b_off;
        const uint32_t blo_base = sbase + OFF_BLO + b_off;

#pragma unroll 1
        for (int ks = 0; ks < 13; ks++) {
            const uint32_t adelta = (uint32_t)ks * 16 * PITCH_A_B;
            uint32_t a[2][4];
            LDSM_X4T(a[0][0], a[0][1], a[0][2], a[0][3], a0_base + adelta);
            LDSM_X4T(a[1][0], a[1][1], a[1][2], a[1][3], a1_base + adelta);
            const uint32_t brow = (uint32_t)ks * 16 * PITCH_B_B;
#pragma unroll
            for (int nbg = 0; nbg < 4; nbg++) {
                uint32_t h0, h1, h2, h3, l0, l1, l2, l3;
                LDSM_X4T(h0, h1, h2, h3, bhi_base + brow + (uint32_t)nbg * 32);
#pragma unroll
                for (int mt = 0; mt < 2; mt++) {
                    MMA16816(acc[mt][2 * nbg],     a[mt][0], a[mt][1], a[mt][2], a[mt][3], h0, h1);
                    MMA16816(acc[mt][2 * nbg + 1], a[mt][0], a[mt][1], a[mt][2], a[mt][3], h2, h3);
                }
                LDSM_X4T(l0, l1, l2, l3, blo_base + brow + (uint32_t)nbg * 32);
#pragma unroll
                for (int mt = 0; mt < 2; mt++) {
                    MMA16816(acc[mt][2 * nbg],     a[mt][0], a[mt][1], a[mt][2], a[mt][3], l0, l1);
                    MMA16816(acc[mt][2 * nbg + 1], a[mt][0], a[mt][1], a[mt][2], a[mt][3], l2, l3);
                }
            }
        }

        // ---- epilogue ----
        const float c1x = 1.f + *eps1p;
        const float c2x = 1.f + *eps2p;
        const int g  = lane >> 2;
        const int tg = lane & 3;

        float s0 = 0.f, s1 = 0.f;
#pragma unroll
        for (int mt = 0; mt < 2; mt++) {
#pragma unroll
            for (int half = 0; half < 2; half++) {       // row r0 (c01) / r0+8 (c23)
                const int j = 32 * mp + 16 * mt + g + half * 8;
                const int jc = (j < N_NODE) ? j : (N_NODE - 1);  // clamped smem row
                float p0 = 0.f, p1 = 0.f;
#pragma unroll
                for (int nt = 0; nt < 8; nt++) {
                    const int f = 64 * nh + nt * 8 + tg * 2;
                    uint32_t hv = *(uint32_t*)(smem + OFF_BHI + jc * PITCH_B_B + f * 2);
                    uint32_t lv = *(uint32_t*)(smem + OFF_BLO + jc * PITCH_B_B + f * 2);
                    float x0 = __uint_as_float(hv << 16) + __uint_as_float(lv << 16);
                    float x1 = __uint_as_float(hv & 0xFFFF0000u)
                             + __uint_as_float(lv & 0xFFFF0000u);
                    float a0 = acc[mt][nt][2 * half + 0];
                    float a1 = acc[mt][nt][2 * half + 1];
                    float h0 = fmaxf(fmaf(c1x, x0, a0) + b1s[f], 0.f);
                    float h1 = fmaxf(fmaf(c1x, x1, a1) + b1s[f + 1], 0.f);
                    p0 += h0 * w2s[f * 2]       + h1 * w2s[(f + 1) * 2];
                    p1 += h0 * w2s[f * 2 + 1]   + h1 * w2s[(f + 1) * 2 + 1];
                }
                float wj = (j < N_NODE) ? (c2x + degs[jc]) : 0.f;
                s0 += p0 * wj;
                s1 += p1 * wj;
            }
        }
        // reduce: tg lanes (1,2) then g groups (4,8,16)
#pragma unroll
        for (int off = 1; off <= 16; off <<= 1) {
            s0 += __shfl_xor_sync(0xffffffffu, s0, off);
            s1 += __shfl_xor_sync(0xffffffffu, s1, off);
        }
        if (lane == 0) { wsum[w * 2 + 0] = s0; wsum[w * 2 + 1] = s1; }
    }
    __syncthreads();

    if (t < 2) {
        float s = 0.f;
#pragma unroll
        for (int q = 0; q < 14; q++) s += wsum[q * 2 + t];
        out[b * 2 + t] = s * (1.f / N_NODE) + b2[t];
    }
}

// ---------------------------------------------------------------------------
extern "C" void kernel_launch(void* const* d_in, const int* in_sizes, int n_in,
                              void* d_out, int out_size)
{
    const float* x    = (const float*)d_in[0];   // [512,200,200]
    const int*   adj  = (const int*)  d_in[1];   // [512,200,200]
    const float* W1   = (const float*)d_in[2];   // [200,128]
    const float* b1   = (const float*)d_in[3];   // [128]
    const float* W2   = (const float*)d_in[4];   // [128,2]
    const float* b2   = (const float*)d_in[5];   // [2]
    const float* eps1 = (const float*)d_in[6];
    const float* eps2 = (const float*)d_in[7];
    float* out = (float*)d_out;                  // [512,2]

    cudaFuncSetAttribute(gemm_xw_mma_kernel,
                         cudaFuncAttributeMaxDynamicSharedMemorySize, K1_SMEM);
    cudaFuncSetAttribute(gin_fused_kernel,
                         cudaFuncAttributeMaxDynamicSharedMemorySize, SMEM_TOTAL);

    split_w1_kernel<<<(208 * HIDDEN + 255) / 256, 256>>>(W1);
    gemm_xw_mma_kernel<<<BATCH * N_NODE / 128, 512, K1_SMEM>>>(x);
    gin_fused_kernel<<<BATCH, 512, SMEM_TOTAL>>>(adj, b1, W2, b2, eps1, eps2, out);
}

// round 15
// speedup vs baseline: 1.4466x; 1.1432x over previous
#include <cuda_runtime.h>
#include <cuda_bf16.h>
#include <cstdint>

#define BATCH  512
#define N_NODE 200
#define C_IN   200
#define HIDDEN 128

typedef unsigned long long ull;

// ===================== PTX helpers =====================
__device__ __forceinline__ uint32_t smem_u32(const void* p) {
    uint32_t a;
    asm("{ .reg .u64 t; cvta.to.shared.u64 t, %1; cvt.u32.u64 %0, t; }"
        : "=r"(a) : "l"(p));
    return a;
}

#define LDSM_X4(r0, r1, r2, r3, addr) \
    asm volatile("ldmatrix.sync.aligned.m8n8.x4.shared.b16 {%0,%1,%2,%3}, [%4];" \
        : "=r"(r0), "=r"(r1), "=r"(r2), "=r"(r3) : "r"(addr))

#define LDSM_X4T(r0, r1, r2, r3, addr) \
    asm volatile("ldmatrix.sync.aligned.m8n8.x4.trans.shared.b16 {%0,%1,%2,%3}, [%4];" \
        : "=r"(r0), "=r"(r1), "=r"(r2), "=r"(r3) : "r"(addr))

#define MMA16816(c, a0, a1, a2, a3, b0, b1) \
    asm volatile("mma.sync.aligned.m16n8k16.row.col.f32.bf16.bf16.f32 " \
        "{%0,%1,%2,%3}, {%4,%5,%6,%7}, {%8,%9}, {%0,%1,%2,%3};" \
        : "+f"((c)[0]), "+f"((c)[1]), "+f"((c)[2]), "+f"((c)[3]) \
        : "r"(a0), "r"(a1), "r"(a2), "r"(a3), "r"(b0), "r"(b1))

#define CP_ASYNC16(dst, src) \
    asm volatile("cp.async.cg.shared.global [%0], [%1], 16;" \
        :: "r"(dst), "l"(src) : "memory")
#define CP_ASYNC_WAIT_ALL() \
    asm volatile("cp.async.commit_group;\n\tcp.async.wait_group 0;" ::: "memory")

__device__ __forceinline__ void split2(float a, float b, uint32_t& hp, uint32_t& lp) {
    __nv_bfloat16 h0 = __float2bfloat16(a);
    __nv_bfloat16 h1 = __float2bfloat16(b);
    __nv_bfloat16 l0 = __float2bfloat16(a - __bfloat162float(h0));
    __nv_bfloat16 l1 = __float2bfloat16(b - __bfloat162float(h1));
    hp = (uint32_t)__bfloat16_as_ushort(h0) | ((uint32_t)__bfloat16_as_ushort(h1) << 16);
    lp = (uint32_t)__bfloat16_as_ushort(l0) | ((uint32_t)__bfloat16_as_ushort(l1) << 16);
}

// W1 pre-split into bf16 hi/lo, zero-padded to K=208 rows: [208][128]
__device__ __nv_bfloat16 g_w1hi[208 * HIDDEN];
__device__ __nv_bfloat16 g_w1lo[208 * HIDDEN];

// ---------------------------------------------------------------------------
// K0: split W1 fp32 -> bf16 hi/lo with zero k-padding (runs once, tiny)
// ---------------------------------------------------------------------------
__global__ void split_w1_kernel(const float* __restrict__ W1)
{
    int idx = blockIdx.x * 256 + threadIdx.x;
    if (idx >= 208 * HIDDEN) return;
    int k = idx / HIDDEN;
    float v = (k < C_IN) ? W1[idx] : 0.f;
    __nv_bfloat16 h = __float2bfloat16(v);
    __nv_bfloat16 l = __float2bfloat16(v - __bfloat162float(h));
    g_w1hi[idx] = h;
    g_w1lo[idx] = l;
}

// ---------------------------------------------------------------------------
// FUSED kernel: one CTA per batch, 512 threads.
//   Phase 1: xw = x[b] @ W1 (split-bf16, 3 products), A streamed in k16
//            chunks (double-buffered), result stored to smem (over W1).
//   Phase 2: agg = adjT @ xw (split-bf16 B, exact A), fused GIN epilogue.
// ---------------------------------------------------------------------------
// smem layout
#define CH_PITCH   48
#define CH0_HI     0                   // 208*48 = 9984 each
#define CH0_LO     9984
#define CH1_HI     19968
#define CH1_LO     29952               // chunk region ends 39936 (+tail pad)
#define PITCH_A    432                 // phase-2 adjT tile pitch
#define OFF_A      0                   // 208*432 = 89856 (overlaps chunks)
#define PITCH_B    272
#define OFF_BHI    89856               // W1 (phase 1) -> xw (phase 2)
#define OFF_BLO    146432              // + 56576
#define OFF_DEG    203008              // 200 floats
#define OFF_WS     203808              // 14*2 floats (pad 128)
#define OFF_B1S    203936              // 128 floats
#define OFF_W2S    204448              // 256 floats
#define SMEM_TOTAL 205504

__global__ __launch_bounds__(512, 1) void gin_fused_all_kernel(
    const float* __restrict__ x,
    const int*   __restrict__ adj,
    const float* __restrict__ b1,
    const float* __restrict__ W2,
    const float* __restrict__ b2,
    const float* __restrict__ eps1p,
    const float* __restrict__ eps2p,
    float*       __restrict__ out)
{
    extern __shared__ char smem[];
    const uint32_t sbase = smem_u32(smem);
    float* degs = (float*)(smem + OFF_DEG);
    float* wsum = (float*)(smem + OFF_WS);
    float* b1s  = (float*)(smem + OFF_B1S);
    float* w2s  = (float*)(smem + OFF_W2S);

    const int b    = blockIdx.x;
    const int t    = threadIdx.x;
    const int w    = t >> 5;
    const int lane = t & 31;
    const float* xb = x + (size_t)b * N_NODE * C_IN;
    const int* adj_b = adj + (size_t)b * N_NODE * N_NODE;

    // ---- issue W1 cp.async (B of phase 1) ----
    for (int idx = t; idx < 208 * 16; idx += 512) {
        const int r = idx >> 4;
        const int c = idx & 15;
        CP_ASYNC16(sbase + OFF_BHI + r * PITCH_B + c * 16,
                   (const char*)g_w1hi + r * 256 + c * 16);
        CP_ASYNC16(sbase + OFF_BLO + r * PITCH_B + c * 16,
                   (const char*)g_w1lo + r * 256 + c * 16);
    }

    // ---- zero chunk pad rows (200..207 x 4 buffers) + overflow tail ----
    {
        const uint4 z = make_uint4(0u, 0u, 0u, 0u);
        for (int idx = t; idx < 96; idx += 512) {
            const int buf = idx / 24;
            const int rr  = (idx % 24) / 3;
            const int c   = idx % 3;
            *(uint4*)(smem + buf * 9984 + (200 + rr) * CH_PITCH + c * 16) = z;
        }
        for (int idx = t; idx < 48; idx += 512)
            *(uint4*)(smem + 39936 + idx * 16) = z;
        if (t < 128) b1s[t] = b1[t];
        if (t < 256) w2s[t] = W2[t];
    }

    // ---- stage chunk 0 (k = 0..15) ----
    {
        for (int idx = t; idx < 800; idx += 512) {
            const int m = idx >> 2, q = idx & 3;
            float4 v = *(const float4*)&xb[m * C_IN + 4 * q];   // k<16 always valid
            uint2 hp, lp;
            split2(v.x, v.y, hp.x, lp.x);
            split2(v.z, v.w, hp.y, lp.y);
            *(uint2*)(smem + CH0_HI + m * CH_PITCH + q * 8) = hp;
            *(uint2*)(smem + CH0_LO + m * CH_PITCH + q * 8) = lp;
        }
    }
    CP_ASYNC_WAIT_ALL();
    __syncthreads();

    // ---- phase 1: xw = x @ W1, warp = (mp = w%7: m32) x (nh = w/7: n64) ----
    const int mp = (w < 14) ? (w % 7) : 0;
    const int nh = (w < 14) ? (w / 7) : 0;
    const int g  = lane >> 2;
    const int tg = lane & 3;

    float acc[2][8][4];
#pragma unroll
    for (int mt = 0; mt < 2; mt++)
#pragma unroll
        for (int n = 0; n < 8; n++) {
            acc[mt][n][0] = 0.f; acc[mt][n][1] = 0.f;
            acc[mt][n][2] = 0.f; acc[mt][n][3] = 0.f;
        }

    const uint32_t a_lane = (uint32_t)(32 * mp + (lane & 15)) * CH_PITCH
                          + (uint32_t)(lane >> 4) * 16;
    const uint32_t b_lane = (uint32_t)(lane & 15) * PITCH_B
                          + (uint32_t)(lane >> 4) * 16 + (uint32_t)nh * 128;

#pragma unroll 1
    for (int ks = 0; ks < 13; ks++) {
        // prefetch next chunk (LDGs issue before MMA; uses after)
        float4 v0, v1;
        const int has1 = (t < 288);
        if (ks < 12) {
            const int k0n = 16 * (ks + 1);
            {
                const int m = t >> 2, q = t & 3, k = k0n + 4 * q;
                v0 = (k < 200) ? *(const float4*)&xb[m * C_IN + k]
                               : make_float4(0.f, 0.f, 0.f, 0.f);
            }
            if (has1) {
                const int idx = t + 512;
                const int m = idx >> 2, q = idx & 3, k = k0n + 4 * q;
                v1 = (k < 200) ? *(const float4*)&xb[m * C_IN + k]
                               : make_float4(0.f, 0.f, 0.f, 0.f);
            }
        }

        // MMA on current buffer
        if (w < 14) {
            const uint32_t ch_hi = sbase + ((ks & 1) ? CH1_HI : CH0_HI) + a_lane;
            const uint32_t ch_lo = ch_hi + 9984;
            uint32_t ah[2][4], al[2][4];
            LDSM_X4(ah[0][0], ah[0][1], ah[0][2], ah[0][3], ch_hi);
            LDSM_X4(ah[1][0], ah[1][1], ah[1][2], ah[1][3], ch_hi + 16 * CH_PITCH);
            LDSM_X4(al[0][0], al[0][1], al[0][2], al[0][3], ch_lo);
            LDSM_X4(al[1][0], al[1][1], al[1][2], al[1][3], ch_lo + 16 * CH_PITCH);
            const uint32_t brow = sbase + OFF_BHI + b_lane + (uint32_t)ks * 16 * PITCH_B;
#pragma unroll
            for (int nbg = 0; nbg < 4; nbg++) {
                uint32_t h0, h1, h2, h3, l0, l1, l2, l3;
                LDSM_X4T(h0, h1, h2, h3, brow + (uint32_t)nbg * 32);
#pragma unroll
                for (int mt = 0; mt < 2; mt++) {
                    MMA16816(acc[mt][2 * nbg],     ah[mt][0], ah[mt][1], ah[mt][2], ah[mt][3], h0, h1);
                    MMA16816(acc[mt][2 * nbg + 1], ah[mt][0], ah[mt][1], ah[mt][2], ah[mt][3], h2, h3);
                    MMA16816(acc[mt][2 * nbg],     al[mt][0], al[mt][1], al[mt][2], al[mt][3], h0, h1);
                    MMA16816(acc[mt][2 * nbg + 1], al[mt][0], al[mt][1], al[mt][2], al[mt][3], h2, h3);
                }
                LDSM_X4T(l0, l1, l2, l3,
                         brow + (uint32_t)(OFF_BLO - OFF_BHI) + (uint32_t)nbg * 32);
#pragma unroll
                for (int mt = 0; mt < 2; mt++) {
                    MMA16816(acc[mt][2 * nbg],     ah[mt][0], ah[mt][1], ah[mt][2], ah[mt][3], l0, l1);
                    MMA16816(acc[mt][2 * nbg + 1], ah[mt][0], ah[mt][1], ah[mt][2], ah[mt][3], l2, l3);
                }
            }
        }

        // store prefetched chunk
        if (ks < 12) {
            const int bofs = ((ks + 1) & 1) ? CH1_HI : CH0_HI;
            {
                const int m = t >> 2, q = t & 3;
                uint2 hp, lp;
                split2(v0.x, v0.y, hp.x, lp.x);
                split2(v0.z, v0.w, hp.y, lp.y);
                *(uint2*)(smem + bofs + m * CH_PITCH + q * 8) = hp;
                *(uint2*)(smem + bofs + 9984 + m * CH_PITCH + q * 8) = lp;
            }
            if (has1) {
                const int idx = t + 512;
                const int m = idx >> 2, q = idx & 3;
                uint2 hp, lp;
                split2(v1.x, v1.y, hp.x, lp.x);
                split2(v1.z, v1.w, hp.y, lp.y);
                *(uint2*)(smem + bofs + m * CH_PITCH + q * 8) = hp;
                *(uint2*)(smem + bofs + 9984 + m * CH_PITCH + q * 8) = lp;
            }
        }
        __syncthreads();
    }

    // ---- store xw fragments (bf16 hi/lo) into former W1 region ----
    if (w < 14) {
#pragma unroll
        for (int mt = 0; mt < 2; mt++) {
            const int ra = 32 * mp + 16 * mt + g;
            const int rb = ra + 8;
#pragma unroll
            for (int nt = 0; nt < 8; nt++) {
                const int f = 64 * nh + nt * 8 + tg * 2;
                uint32_t hp, lp;
                if (ra < 208) {
                    split2(acc[0 + mt == mt ? mt : mt][nt][0], acc[mt][nt][1], hp, lp);
                    *(uint32_t*)(smem + OFF_BHI + ra * PITCH_B + f * 2) = hp;
                    *(uint32_t*)(smem + OFF_BLO + ra * PITCH_B + f * 2) = lp;
                }
                if (rb < 208) {
                    split2(acc[mt][nt][2], acc[mt][nt][3], hp, lp);
                    *(uint32_t*)(smem + OFF_BHI + rb * PITCH_B + f * 2) = hp;
                    *(uint32_t*)(smem + OFF_BLO + rb * PITCH_B + f * 2) = lp;
                }
            }
        }
    }

    // ---- phase 2 staging: adjA pads, adj (non-transposed) + row degrees ----
    {
        const uint4 z = make_uint4(0u, 0u, 0u, 0u);
        for (int r = t; r < 200; r += 512) {
            char* p = smem + OFF_A + r * PITCH_A;
            *(uint4*)(p + 400) = z;
            *(uint4*)(p + 416) = z;
        }
        for (int idx = t; idx < 8 * 27; idx += 512) {
            const int r = 200 + idx / 27;
            const int c = idx % 27;
            *(uint4*)(smem + OFF_A + r * PITCH_A + c * 16) = z;
        }
        for (int i = w; i < N_NODE; i += 16) {
            const int* row = &adj_b[i * N_NODE];
            char* dst = smem + OFF_A + i * PITCH_A;
            int rsum = 0;
#pragma unroll
            for (int c = 0; c < 7; c++) {
                const int j = lane + 32 * c;
                if (j < N_NODE) {
                    int v = row[j];
                    *(unsigned short*)(dst + j * 2) =
                        v ? (unsigned short)0x3F80u : (unsigned short)0u;
                    rsum += v;
                }
            }
#pragma unroll
            for (int off = 16; off; off >>= 1)
                rsum += __shfl_xor_sync(0xffffffffu, rsum, off);
            if (lane == 0) degs[i] = (float)rsum;
        }
    }
    __syncthreads();

    // ---- phase 2 MMA: agg = adjT @ xw (warps 0..13, m32 x n64) ----
    if (w < 14) {
#pragma unroll
        for (int mt = 0; mt < 2; mt++)
#pragma unroll
            for (int n = 0; n < 8; n++) {
                acc[mt][n][0] = 0.f; acc[mt][n][1] = 0.f;
                acc[mt][n][2] = 0.f; acc[mt][n][3] = 0.f;
            }

        const uint32_t a_row = (uint32_t)((lane & 7) + ((lane >> 4) << 3)) * PITCH_A;
        const uint32_t a0_base = sbase + OFF_A + a_row
            + (uint32_t)(32 * mp + ((lane >> 3) & 1) * 8) * 2;
        const uint32_t a1_base = a0_base + 32;
        const uint32_t bhi_base = sbase + OFF_BHI + b_lane;
        const uint32_t blo_base = sbase + OFF_BLO + b_lane;

#pragma unroll 1
        for (int ks = 0; ks < 13; ks++) {
            const uint32_t adelta = (uint32_t)ks * 16 * PITCH_A;
            uint32_t a[2][4];
            LDSM_X4T(a[0][0], a[0][1], a[0][2], a[0][3], a0_base + adelta);
            LDSM_X4T(a[1][0], a[1][1], a[1][2], a[1][3], a1_base + adelta);
            const uint32_t brow = (uint32_t)ks * 16 * PITCH_B;
#pragma unroll
            for (int nbg = 0; nbg < 4; nbg++) {
                uint32_t h0, h1, h2, h3, l0, l1, l2, l3;
                LDSM_X4T(h0, h1, h2, h3, bhi_base + brow + (uint32_t)nbg * 32);
#pragma unroll
                for (int mt = 0; mt < 2; mt++) {
                    MMA16816(acc[mt][2 * nbg],     a[mt][0], a[mt][1], a[mt][2], a[mt][3], h0, h1);
                    MMA16816(acc[mt][2 * nbg + 1], a[mt][0], a[mt][1], a[mt][2], a[mt][3], h2, h3);
                }
                LDSM_X4T(l0, l1, l2, l3, blo_base + brow + (uint32_t)nbg * 32);
#pragma unroll
                for (int mt = 0; mt < 2; mt++) {
                    MMA16816(acc[mt][2 * nbg],     a[mt][0], a[mt][1], a[mt][2], a[mt][3], l0, l1);
                    MMA16816(acc[mt][2 * nbg + 1], a[mt][0], a[mt][1], a[mt][2], a[mt][3], l2, l3);
                }
            }
        }

        // ---- epilogue ----
        const float c1x = 1.f + *eps1p;
        const float c2x = 1.f + *eps2p;

        float s0 = 0.f, s1 = 0.f;
#pragma unroll
        for (int mt = 0; mt < 2; mt++) {
#pragma unroll
            for (int half = 0; half < 2; half++) {
                const int j = 32 * mp + 16 * mt + g + half * 8;
                const int jc = (j < N_NODE) ? j : (N_NODE - 1);
                float p0 = 0.f, p1 = 0.f;
#pragma unroll
                for (int nt = 0; nt < 8; nt++) {
                    const int f = 64 * nh + nt * 8 + tg * 2;
                    uint32_t hv = *(uint32_t*)(smem + OFF_BHI + jc * PITCH_B + f * 2);
                    uint32_t lv = *(uint32_t*)(smem + OFF_BLO + jc * PITCH_B + f * 2);
                    float x0 = __uint_as_float(hv << 16) + __uint_as_float(lv << 16);
                    float x1 = __uint_as_float(hv & 0xFFFF0000u)
                             + __uint_as_float(lv & 0xFFFF0000u);
                    float a0 = acc[mt][nt][2 * half + 0];
                    float a1 = acc[mt][nt][2 * half + 1];
                    float h0 = fmaxf(fmaf(c1x, x0, a0) + b1s[f], 0.f);
                    float h1 = fmaxf(fmaf(c1x, x1, a1) + b1s[f + 1], 0.f);
                    p0 += h0 * w2s[f * 2]     + h1 * w2s[(f + 1) * 2];
                    p1 += h0 * w2s[f * 2 + 1] + h1 * w2s[(f + 1) * 2 + 1];
                }
                float wj = (j < N_NODE) ? (c2x + degs[jc]) : 0.f;
                s0 += p0 * wj;
                s1 += p1 * wj;
            }
        }
#pragma unroll
        for (int off = 1; off <= 16; off <<= 1) {
            s0 += __shfl_xor_sync(0xffffffffu, s0, off);
            s1 += __shfl_xor_sync(0xffffffffu, s1, off);
        }
        if (lane == 0) { wsum[w * 2 + 0] = s0; wsum[w * 2 + 1] = s1; }
    }
    __syncthreads();

    if (t < 2) {
        float s = 0.f;
#pragma unroll
        for (int q = 0; q < 14; q++) s += wsum[q * 2 + t];
        out[b * 2 + t] = s * (1.f / N_NODE) + b2[t];
    }
}

// ---------------------------------------------------------------------------
extern "C" void kernel_launch(void* const* d_in, const int* in_sizes, int n_in,
                              void* d_out, int out_size)
{
    const float* x    = (const float*)d_in[0];   // [512,200,200]
    const int*   adj  = (const int*)  d_in[1];   // [512,200,200]
    const float* W1   = (const float*)d_in[2];   // [200,128]
    const float* b1   = (const float*)d_in[3];   // [128]
    const float* W2   = (const float*)d_in[4];   // [128,2]
    const float* b2   = (const float*)d_in[5];   // [2]
    const float* eps1 = (const float*)d_in[6];
    const float* eps2 = (const float*)d_in[7];
    float* out = (float*)d_out;                  // [512,2]

    cudaFuncSetAttribute(gin_fused_all_kernel,
                         cudaFuncAttributeMaxDynamicSharedMemorySize, SMEM_TOTAL);

    split_w1_kernel<<<(208 * HIDDEN + 255) / 256, 256>>>(W1);
    gin_fused_all_kernel<<<BATCH, 512, SMEM_TOTAL>>>(x, adj, b1, W2, b2,
                                                     eps1, eps2, out);
}